// round 2
// baseline (speedup 1.0000x reference)
#include <cuda_runtime.h>
#include <cuda_bf16.h>
#include <math.h>

#define FULLMASK 0xffffffffu

static const int N_ROI = 116;
static const int G     = 128;
static const int DEG   = 32;
static const int NN    = G * N_ROI;        // 14848 nodes
static const int EE    = G * N_ROI * DEG;  // 475136 edges
static const int EPG   = N_ROI * DEG;      // 3712 edges per graph
static const int HID   = 64;
static const int HC    = 256;
static const int MAXDEG = 192;

// ---------------- device scratch (allocation-free) ----------------
__device__ float g_h0[NN * HID];        // post-embed
__device__ float g_h1[NN * HID];        // post GINE+MLP+LN
__device__ float g_xl[NN * HC];
__device__ float g_xr[NN * HC];
__device__ float g_out[NN * HC];        // GAT layer output (raw, pre-BN)
__device__ int   g_nodelist[NN * MAXDEG];
__device__ int   g_deg[NN];
__device__ float g_csum[HC];
__device__ float g_csq[HC];

// ---------------- f32x2 packed-FMA helpers (Blackwell) ----------------
__device__ __forceinline__ unsigned long long pk2(float lo, float hi) {
    unsigned long long r;
    asm("mov.b64 %0, {%1, %2};" : "=l"(r) : "f"(lo), "f"(hi));
    return r;
}
__device__ __forceinline__ void ffma2(unsigned long long& d, unsigned long long a,
                                      unsigned long long b) {
    asm("fma.rn.f32x2 %0, %1, %2, %0;" : "+l"(d) : "l"(a), "l"(b));
}
__device__ __forceinline__ void unpk2(float& lo, float& hi, unsigned long long v) {
    asm("mov.b64 {%0, %1}, %2;" : "=f"(lo), "=f"(hi) : "l"(v));
}

// ---------------- adjacency build: warp per node, ordered ballot compaction ----
__global__ void build_adj_k(const int* __restrict__ dst) {
    int gw = (blockIdx.x * blockDim.x + threadIdx.x) >> 5;
    if (gw >= NN) return;
    int lane = threadIdx.x & 31;
    int n = gw;
    int g = n / N_ROI;
    int ebase = g * EPG;
    int count = 0;
    int* out = g_nodelist + n * MAXDEG;
    for (int i = 0; i < EPG; i += 32) {
        int e = ebase + i + lane;
        int d = dst[e];
        unsigned m = __ballot_sync(FULLMASK, d == n);
        if (d == n) {
            int rank = __popc(m & ((1u << lane) - 1u));
            int pos = count + rank;
            if (pos < MAXDEG) out[pos] = e;
        }
        count += __popc(m);
    }
    if (lane == 0) g_deg[n] = min(count, MAXDEG);
}

// ---------------- node embed ----------------
__global__ void embed_k(const float* __restrict__ x, const int* __restrict__ node_group,
                        const float* __restrict__ gemb, const float* __restrict__ W,
                        const float* __restrict__ b) {
    int n = blockIdx.x;
    int t = threadIdx.x;   // 64
    __shared__ float sx[132];
    for (int i = t; i < 116; i += 64) sx[i] = x[n * 116 + i];
    if (t < 16) sx[116 + t] = gemb[node_group[n] * 16 + t];
    __syncthreads();
    float acc = b[t];
    #pragma unroll 4
    for (int r = 0; r < 132; r++) acc += sx[r] * W[r * 64 + t];
    g_h0[n * 64 + t] = acc >= 0.f ? acc : 0.01f * acc;
}

// ---------------- GINE aggregate + MLP + LayerNorm ----------------
__global__ void gine_k(const int* __restrict__ srcA, const float* __restrict__ ea,
                       const float* __restrict__ We, const float* __restrict__ be,
                       const float* __restrict__ W1, const float* __restrict__ b1,
                       const float* __restrict__ W2, const float* __restrict__ b2,
                       const float* __restrict__ lng, const float* __restrict__ lnb) {
    int n = blockIdx.x;
    int t = threadIdx.x;   // 64
    __shared__ float sh[64], sh2[64], ws[2], wq[2];
    float s = g_h0[n * 64 + t];
    int d = g_deg[n];
    const int* lst = g_nodelist + n * MAXDEG;
    float bec = be[t];
    float w0 = We[t], w1 = We[64 + t], w2 = We[128 + t], w3 = We[192 + t], w4 = We[256 + t];
    for (int i = 0; i < d; i++) {
        int e = lst[i];
        int src = srcA[e];
        const float* a = ea + (long)e * 5;
        float em = bec + a[0] * w0 + a[1] * w1 + a[2] * w2 + a[3] * w3 + a[4] * w4;
        em = em >= 0.f ? em : 0.01f * em;
        float v = g_h0[src * 64 + t] + em;
        s += v > 0.f ? v : 0.f;
    }
    sh[t] = s;
    __syncthreads();
    float acc = b1[t];
    #pragma unroll 8
    for (int r = 0; r < 64; r++) acc += sh[r] * W1[r * 64 + t];
    acc = acc >= 0.f ? acc : 0.01f * acc;
    sh2[t] = acc;
    __syncthreads();
    float acc2 = b2[t];
    #pragma unroll 8
    for (int r = 0; r < 64; r++) acc2 += sh2[r] * W2[r * 64 + t];
    acc2 = acc2 >= 0.f ? acc2 : 0.01f * acc2;
    float su = acc2, sq = acc2 * acc2;
    for (int o = 16; o; o >>= 1) {
        su += __shfl_down_sync(FULLMASK, su, o);
        sq += __shfl_down_sync(FULLMASK, sq, o);
    }
    if ((t & 31) == 0) { ws[t >> 5] = su; wq[t >> 5] = sq; }
    __syncthreads();
    float mu  = (ws[0] + ws[1]) * (1.f / 64.f);
    float var = (wq[0] + wq[1]) * (1.f / 64.f) - mu * mu;
    g_h1[n * 64 + t] = (acc2 - mu) * rsqrtf(var + 1e-5f) * lng[t] + lnb[t];
}

// ---------------- xl/xr projections, packed f32x2 FMA (xl, xr in lane pair) ---
// LAYER 1 fuses the preceding BatchNorm + leaky into the input load.
template <int LAYER>
__global__ void xlxr_k(const float* __restrict__ Wl, const float* __restrict__ Wr,
                       const float* __restrict__ bng, const float* __restrict__ bnb) {
    constexpr int D = LAYER ? HC : HID;
    int nb = blockIdx.x * 16;
    int t = threadIdx.x;   // 256
    __shared__ unsigned long long sh2[16][D];   // h duplicated into both f32x2 lanes
    if (LAYER == 0) {
        for (int i = t; i < 16 * 64; i += 256) {
            int j = i >> 6, c = i & 63;
            float v = g_h1[(nb + j) * 64 + c];
            sh2[j][c] = pk2(v, v);
        }
    } else {
        for (int i = t; i < 16 * 256; i += 256) {
            int j = i >> 8, c = i & 255;
            float mu  = g_csum[c] * (1.f / NN);
            float var = g_csq[c] * (1.f / NN) - mu * mu;
            float v = g_out[(nb + j) * 256 + c];
            v = (v - mu) * rsqrtf(var + 1e-5f) * bng[c] + bnb[c];
            v = v >= 0.f ? v : 0.01f * v;
            sh2[j][c] = pk2(v, v);
        }
    }
    __syncthreads();
    unsigned long long acc[16];
    #pragma unroll
    for (int j = 0; j < 16; j++) acc[j] = 0ull;
    #pragma unroll 4
    for (int r = 0; r < D; r++) {
        unsigned long long w2 = pk2(Wl[r * 256 + t], Wr[r * 256 + t]);
        #pragma unroll
        for (int j = 0; j < 16; j++) ffma2(acc[j], sh2[j][r], w2);
    }
    #pragma unroll
    for (int j = 0; j < 16; j++) {
        float lo, hi;
        unpk2(lo, hi, acc[j]);
        g_xl[(nb + j) * 256 + t] = lo;
        g_xr[(nb + j) * 256 + t] = hi;
    }
}

// ---------------- GATv2: block per (graph, head), SMEM-resident ----------------
// smem: sxl[116*64] | sxr[116*64] | slog[3712] | ssrc[3712] (u16)
static const int SMEM_GAT = (116 * 64 * 2 + EPG) * 4 + EPG * 2;   // 81664 B

__global__ void gat_graph_k(const int* __restrict__ srcA, const int* __restrict__ dstA,
                            const float* __restrict__ ea,
                            const float* __restrict__ WeP,   // [5,256]
                            const float* __restrict__ attF)  // [4*64]
{
    int g = blockIdx.x >> 2;
    int h = blockIdx.x & 3;
    extern __shared__ float smem[];
    float* sxl = smem;
    float* sxr = sxl + 116 * 64;
    float* slog = sxr + 116 * 64;
    unsigned short* ssrc = (unsigned short*)(slog + EPG);
    int t = threadIdx.x, lane = t & 31, wid = t >> 5;
    int nbase = g * N_ROI, ebase = g * EPG;

    // A: load xl/xr head slices
    for (int i = t; i < 116 * 64; i += 256) {
        int n = i >> 6, c = i & 63;
        sxl[i] = g_xl[(nbase + n) * 256 + h * 64 + c];
        sxr[i] = g_xr[(nbase + n) * 256 + h * 64 + c];
    }
    float wp[5], wq[5];
    #pragma unroll
    for (int k = 0; k < 5; k++) {
        wp[k] = WeP[k * 256 + h * 64 + lane];
        wq[k] = WeP[k * 256 + h * 64 + 32 + lane];
    }
    float a1 = attF[h * 64 + lane], a2 = attF[h * 64 + 32 + lane];
    __syncthreads();

    // B: logits, warp per edge
    for (int el = wid; el < EPG; el += 8) {
        int e = ebase + el;
        int s  = srcA[e] - nbase;
        int dn = dstA[e] - nbase;
        const float* a = ea + (long)e * 5;
        float e0 = a[0], e1 = a[1], e2 = a[2], e3 = a[3], e4 = a[4];
        float ep1 = e0 * wp[0] + e1 * wp[1] + e2 * wp[2] + e3 * wp[3] + e4 * wp[4];
        float ep2 = e0 * wq[0] + e1 * wq[1] + e2 * wq[2] + e3 * wq[3] + e4 * wq[4];
        float z1 = sxl[s * 64 + lane]      + sxr[dn * 64 + lane]      + ep1;
        float z2 = sxl[s * 64 + 32 + lane] + sxr[dn * 64 + 32 + lane] + ep2;
        z1 = z1 >= 0.f ? z1 : 0.2f * z1;
        z2 = z2 >= 0.f ? z2 : 0.2f * z2;
        float v = z1 * a1 + z2 * a2;
        #pragma unroll
        for (int o = 16; o; o >>= 1) v += __shfl_down_sync(FULLMASK, v, o);
        if (lane == 0) {
            slog[el] = v;
            ssrc[el] = (unsigned short)s;
        }
    }
    __syncthreads();

    // C: softmax per node, warp per node
    for (int n = wid; n < N_ROI; n += 8) {
        int d = g_deg[nbase + n];
        const int* lst = g_nodelist + (nbase + n) * MAXDEG;
        float m = -1e30f;
        for (int i = lane; i < d; i += 32) m = fmaxf(m, slog[lst[i] - ebase]);
        #pragma unroll
        for (int o = 16; o; o >>= 1) m = fmaxf(m, __shfl_xor_sync(FULLMASK, m, o));
        float ssum = 0.f;
        for (int i = lane; i < d; i += 32) {
            int q = lst[i] - ebase;
            float ex = __expf(slog[q] - m);
            slog[q] = ex;
            ssum += ex;
        }
        #pragma unroll
        for (int o = 16; o; o >>= 1) ssum += __shfl_xor_sync(FULLMASK, ssum, o);
        float inv = 1.f / (ssum + 1e-16f);
        for (int i = lane; i < d; i += 32) slog[lst[i] - ebase] *= inv;
    }
    __syncthreads();

    // D: weighted aggregation, 4 nodes in parallel (64 threads per node)
    int sub = t >> 6, c = t & 63;
    for (int n0 = 0; n0 < N_ROI; n0 += 4) {
        int n = n0 + sub;   // 116 % 4 == 0
        int d = g_deg[nbase + n];
        const int* lst = g_nodelist + (nbase + n) * MAXDEG;
        float acc = 0.f;
        for (int i = 0; i < d; i++) {
            int q = lst[i] - ebase;
            acc += sxl[(int)ssrc[q] * 64 + c] * slog[q];
        }
        g_out[(nbase + n) * 256 + h * 64 + c] = acc;   // bias absorbed by BN
    }
}

// ---------------- BatchNorm statistics ----------------
__global__ void zero_stats_k() {
    int t = threadIdx.x;
    g_csum[t] = 0.f;
    g_csq[t]  = 0.f;
}

__global__ void bnstat_k() {
    int t = threadIdx.x;  // 256 = channel
    int rows = (NN + gridDim.x - 1) / gridDim.x;
    int r0 = blockIdx.x * rows;
    int r1 = min(NN, r0 + rows);
    float s = 0.f, q = 0.f;
    for (int r = r0; r < r1; r++) {
        float v = g_out[r * 256 + t];
        s += v;
        q += v * v;
    }
    atomicAdd(&g_csum[t], s);
    atomicAdd(&g_csq[t], q);
}

// ---------------- pool + classifier (BN+leaky fused in) ----------------
__global__ void pool_k(const float* __restrict__ W, const float* __restrict__ bb,
                       const float* __restrict__ gam, const float* __restrict__ bet,
                       float* __restrict__ outp) {
    int g = blockIdx.x;   // 128 graphs
    int t = threadIdx.x;  // 256 = channel
    float mu  = g_csum[t] * (1.f / NN);
    float var = g_csq[t] * (1.f / NN) - mu * mu;
    float rs = rsqrtf(var + 1e-5f) * gam[t];
    float bt = bet[t];
    float s = 0.f;
    int base = g * N_ROI;
    for (int r = 0; r < N_ROI; r++) {
        float v = g_out[(base + r) * 256 + t];
        v = (v - mu) * rs + bt;
        v = v >= 0.f ? v : 0.01f * v;
        s += v;
    }
    s *= (1.f / (float)N_ROI);
    float c0 = s * W[t * 2], c1 = s * W[t * 2 + 1];
    __shared__ float r0s[8], r1s[8];
    for (int o = 16; o; o >>= 1) {
        c0 += __shfl_down_sync(FULLMASK, c0, o);
        c1 += __shfl_down_sync(FULLMASK, c1, o);
    }
    if ((t & 31) == 0) { r0s[t >> 5] = c0; r1s[t >> 5] = c1; }
    __syncthreads();
    if (t == 0) {
        float a = 0.f, b2 = 0.f;
        for (int i = 0; i < 8; i++) { a += r0s[i]; b2 += r1s[i]; }
        outp[g * 2]     = a  + bb[0];
        outp[g * 2 + 1] = b2 + bb[1];
    }
}

// ---------------- launch --------------------------------------------------------
extern "C" void kernel_launch(void* const* d_in, const int* in_sizes, int n_in,
                              void* d_out, int out_size) {
    const float* x          = (const float*)d_in[0];
    const int*   edge_index = (const int*)  d_in[1];
    const float* edge_attr  = (const float*)d_in[2];
    const int*   node_group = (const int*)  d_in[4];
    const float* group_emb  = (const float*)d_in[5];
    const float* W_embed    = (const float*)d_in[6];
    const float* b_embed    = (const float*)d_in[7];
    const float* We_enc     = (const float*)d_in[8];
    const float* be_enc     = (const float*)d_in[9];
    const float* W1         = (const float*)d_in[10];
    const float* b1         = (const float*)d_in[11];
    const float* W2         = (const float*)d_in[12];
    const float* b2         = (const float*)d_in[13];
    const float* ln_g       = (const float*)d_in[14];
    const float* ln_b       = (const float*)d_in[15];
    const float* l0_Wl      = (const float*)d_in[16];
    const float* l0_Wr      = (const float*)d_in[17];
    const float* l0_We      = (const float*)d_in[18];
    const float* l0_att     = (const float*)d_in[19];
    const float* l0_bn_g    = (const float*)d_in[21];
    const float* l0_bn_b    = (const float*)d_in[22];
    const float* l1_Wl      = (const float*)d_in[23];
    const float* l1_Wr      = (const float*)d_in[24];
    const float* l1_We      = (const float*)d_in[25];
    const float* l1_att     = (const float*)d_in[26];
    const float* l1_bn_g    = (const float*)d_in[28];
    const float* l1_bn_b    = (const float*)d_in[29];
    const float* fc2_W      = (const float*)d_in[30];
    const float* fc2_b      = (const float*)d_in[31];

    const int* srcp = edge_index;
    const int* dstp = edge_index + EE;

    static int smem_set = 0;
    if (!smem_set) {
        cudaFuncSetAttribute(gat_graph_k, cudaFuncAttributeMaxDynamicSharedMemorySize, SMEM_GAT);
        smem_set = 1;
    }

    build_adj_k<<<(NN * 32 + 255) / 256, 256>>>(dstp);
    embed_k<<<NN, 64>>>(x, node_group, group_emb, W_embed, b_embed);
    gine_k<<<NN, 64>>>(srcp, edge_attr, We_enc, be_enc, W1, b1, W2, b2, ln_g, ln_b);

    // GAT layer 0
    xlxr_k<0><<<NN / 16, 256>>>(l0_Wl, l0_Wr, nullptr, nullptr);
    gat_graph_k<<<G * 4, 256, SMEM_GAT>>>(srcp, dstp, edge_attr, l0_We, l0_att);
    zero_stats_k<<<1, 256>>>();
    bnstat_k<<<256, 256>>>();

    // GAT layer 1 (BN of layer-0 fused into xlxr input load)
    xlxr_k<1><<<NN / 16, 256>>>(l1_Wl, l1_Wr, l0_bn_g, l0_bn_b);
    gat_graph_k<<<G * 4, 256, SMEM_GAT>>>(srcp, dstp, edge_attr, l1_We, l1_att);
    zero_stats_k<<<1, 256>>>();
    bnstat_k<<<256, 256>>>();

    // pool + classifier (BN of layer-1 fused in)
    pool_k<<<G, 256>>>(fc2_W, fc2_b, l1_bn_g, l1_bn_b, (float*)d_out);
}

// round 3
// speedup vs baseline: 1.3360x; 1.3360x over previous
#include <cuda_runtime.h>
#include <cuda_bf16.h>
#include <math.h>

#define FULLMASK 0xffffffffu

static const int N_ROI = 116;
static const int G     = 128;
static const int DEG   = 32;
static const int NN    = G * N_ROI;        // 14848 nodes
static const int EE    = G * N_ROI * DEG;  // 475136 edges
static const int EPG   = N_ROI * DEG;      // 3712 edges per graph
static const int HID   = 64;
static const int HC    = 256;
static const int MAXDEG = 192;

// ---------------- device scratch (allocation-free) ----------------
__device__ float g_h0[NN * HID];        // post-embed
__device__ float g_h1[NN * HID];        // post GINE+MLP+LN
__device__ float g_xl[NN * HC];
__device__ float g_xr[NN * HC];
__device__ float g_out[NN * HC];        // GAT layer output (raw, pre-BN)
__device__ int   g_nodelist[NN * MAXDEG];
__device__ int   g_deg[NN];
__device__ float g_csum[HC];
__device__ float g_csq[HC];

// ---------------- f32x2 packed-FMA helpers (Blackwell) ----------------
__device__ __forceinline__ unsigned long long pk2(float lo, float hi) {
    unsigned long long r;
    asm("mov.b64 %0, {%1, %2};" : "=l"(r) : "f"(lo), "f"(hi));
    return r;
}
__device__ __forceinline__ void ffma2(unsigned long long& d, unsigned long long a,
                                      unsigned long long b) {
    asm("fma.rn.f32x2 %0, %1, %2, %0;" : "+l"(d) : "l"(a), "l"(b));
}
__device__ __forceinline__ void unpk2(float& lo, float& hi, unsigned long long v) {
    asm("mov.b64 {%0, %1}, %2;" : "=f"(lo), "=f"(hi) : "l"(v));
}

// ---------------- adjacency build: warp per node, ordered ballot compaction ----
__global__ void build_adj_k(const int* __restrict__ dst) {
    int gw = (blockIdx.x * blockDim.x + threadIdx.x) >> 5;
    if (gw >= NN) return;
    int lane = threadIdx.x & 31;
    int n = gw;
    int g = n / N_ROI;
    int ebase = g * EPG;
    int count = 0;
    int* out = g_nodelist + n * MAXDEG;
    for (int i = 0; i < EPG; i += 32) {
        int e = ebase + i + lane;
        int d = dst[e];
        unsigned m = __ballot_sync(FULLMASK, d == n);
        if (d == n) {
            int rank = __popc(m & ((1u << lane) - 1u));
            int pos = count + rank;
            if (pos < MAXDEG) out[pos] = e;
        }
        count += __popc(m);
    }
    if (lane == 0) g_deg[n] = min(count, MAXDEG);
}

// ---------------- node embed ----------------
__global__ void embed_k(const float* __restrict__ x, const int* __restrict__ node_group,
                        const float* __restrict__ gemb, const float* __restrict__ W,
                        const float* __restrict__ b) {
    int n = blockIdx.x;
    int t = threadIdx.x;   // 64
    __shared__ float sx[132];
    for (int i = t; i < 116; i += 64) sx[i] = x[n * 116 + i];
    if (t < 16) sx[116 + t] = gemb[node_group[n] * 16 + t];
    __syncthreads();
    float acc = b[t];
    #pragma unroll 4
    for (int r = 0; r < 132; r++) acc += sx[r] * W[r * 64 + t];
    g_h0[n * 64 + t] = acc >= 0.f ? acc : 0.01f * acc;
}

// ---------------- GINE aggregate + MLP + LayerNorm ----------------
__global__ void gine_k(const int* __restrict__ srcA, const float* __restrict__ ea,
                       const float* __restrict__ We, const float* __restrict__ be,
                       const float* __restrict__ W1, const float* __restrict__ b1,
                       const float* __restrict__ W2, const float* __restrict__ b2,
                       const float* __restrict__ lng, const float* __restrict__ lnb) {
    int n = blockIdx.x;
    int t = threadIdx.x;   // 64
    __shared__ float sh[64], sh2[64], ws[2], wq[2];
    float s = g_h0[n * 64 + t];
    int d = g_deg[n];
    const int* lst = g_nodelist + n * MAXDEG;
    float bec = be[t];
    float w0 = We[t], w1 = We[64 + t], w2 = We[128 + t], w3 = We[192 + t], w4 = We[256 + t];
    for (int i = 0; i < d; i++) {
        int e = lst[i];
        int src = srcA[e];
        const float* a = ea + (long)e * 5;
        float em = bec + a[0] * w0 + a[1] * w1 + a[2] * w2 + a[3] * w3 + a[4] * w4;
        em = em >= 0.f ? em : 0.01f * em;
        float v = g_h0[src * 64 + t] + em;
        s += v > 0.f ? v : 0.f;
    }
    sh[t] = s;
    __syncthreads();
    float acc = b1[t];
    #pragma unroll 8
    for (int r = 0; r < 64; r++) acc += sh[r] * W1[r * 64 + t];
    acc = acc >= 0.f ? acc : 0.01f * acc;
    sh2[t] = acc;
    __syncthreads();
    float acc2 = b2[t];
    #pragma unroll 8
    for (int r = 0; r < 64; r++) acc2 += sh2[r] * W2[r * 64 + t];
    acc2 = acc2 >= 0.f ? acc2 : 0.01f * acc2;
    float su = acc2, sq = acc2 * acc2;
    for (int o = 16; o; o >>= 1) {
        su += __shfl_down_sync(FULLMASK, su, o);
        sq += __shfl_down_sync(FULLMASK, sq, o);
    }
    if ((t & 31) == 0) { ws[t >> 5] = su; wq[t >> 5] = sq; }
    __syncthreads();
    float mu  = (ws[0] + ws[1]) * (1.f / 64.f);
    float var = (wq[0] + wq[1]) * (1.f / 64.f) - mu * mu;
    g_h1[n * 64 + t] = (acc2 - mu) * rsqrtf(var + 1e-5f) * lng[t] + lnb[t];
}

// ---------------- xlxr layer 0: scalar (load-bound, D=64) ----------------
__global__ void xlxr0_k(const float* __restrict__ Wl, const float* __restrict__ Wr) {
    int nb = blockIdx.x * 16;
    int t = threadIdx.x;   // 256
    __shared__ float sh[16][HID];
    for (int i = t; i < 16 * 64; i += 256) {
        int j = i >> 6, c = i & 63;
        sh[j][c] = g_h1[(nb + j) * 64 + c];
    }
    __syncthreads();
    float al[16], ar[16];
    #pragma unroll
    for (int j = 0; j < 16; j++) { al[j] = 0.f; ar[j] = 0.f; }
    for (int r = 0; r < 64; r++) {
        float wl = Wl[r * 256 + t], wr = Wr[r * 256 + t];
        #pragma unroll
        for (int j = 0; j < 16; j++) {
            float hv = sh[j][r];
            al[j] += hv * wl;
            ar[j] += hv * wr;
        }
    }
    #pragma unroll
    for (int j = 0; j < 16; j++) {
        g_xl[(nb + j) * 256 + t] = al[j];
        g_xr[(nb + j) * 256 + t] = ar[j];
    }
}

// ---------------- xlxr layer 1: f32x2 packed FMA, BN of layer 0 fused in ------
__global__ void xlxr1_k(const float* __restrict__ Wl, const float* __restrict__ Wr,
                        const float* __restrict__ bng, const float* __restrict__ bnb) {
    int nb = blockIdx.x * 16;
    int t = threadIdx.x;   // 256
    __shared__ unsigned long long sh2[16][HC];   // h duplicated into both f32x2 lanes
    for (int i = t; i < 16 * 256; i += 256) {
        int j = i >> 8, c = i & 255;
        float mu  = g_csum[c] * (1.f / NN);
        float var = g_csq[c] * (1.f / NN) - mu * mu;
        float v = g_out[(nb + j) * 256 + c];
        v = (v - mu) * rsqrtf(var + 1e-5f) * bng[c] + bnb[c];
        v = v >= 0.f ? v : 0.01f * v;
        sh2[j][c] = pk2(v, v);
    }
    __syncthreads();
    unsigned long long acc[16];
    #pragma unroll
    for (int j = 0; j < 16; j++) acc[j] = 0ull;
    #pragma unroll 4
    for (int r = 0; r < 256; r++) {
        unsigned long long w2 = pk2(Wl[r * 256 + t], Wr[r * 256 + t]);
        #pragma unroll
        for (int j = 0; j < 16; j++) ffma2(acc[j], sh2[j][r], w2);
    }
    #pragma unroll
    for (int j = 0; j < 16; j++) {
        float lo, hi;
        unpk2(lo, hi, acc[j]);
        g_xl[(nb + j) * 256 + t] = lo;
        g_xr[(nb + j) * 256 + t] = hi;
    }
}

// ---------------- fused GATv2: logits + softmax + aggregate (block per node) ---
__global__ void gat_node_k(const int* __restrict__ srcA, const float* __restrict__ ea,
                           const float* __restrict__ WeP,   // [5,256]
                           const float* __restrict__ attF)  // [4*64] flattened
{
    int n = blockIdx.x;
    int t = threadIdx.x;     // 256
    int lane = t & 31, wid = t >> 5;
    int hh = wid & 3, epair = wid >> 2;
    __shared__ float sxr[256];
    __shared__ float slog[MAXDEG * 4];
    __shared__ int   ssrc[MAXDEG];
    sxr[t] = g_xr[n * 256 + t];
    __syncthreads();
    int d = g_deg[n];
    const int* lst = g_nodelist + n * MAXDEG;
    int k1 = hh * 64 + lane, k2 = k1 + 32;
    float a1 = attF[k1], a2 = attF[k2];
    // phase 1: warp per (edge, head) computes attention logit
    for (int i = epair; i < d; i += 2) {
        int e = lst[i];
        int s = srcA[e];
        const float* a = ea + (long)e * 5;
        float e0 = a[0], e1 = a[1], e2 = a[2], e3 = a[3], e4 = a[4];
        float ep1 = e0 * WeP[k1] + e1 * WeP[256 + k1] + e2 * WeP[512 + k1]
                  + e3 * WeP[768 + k1] + e4 * WeP[1024 + k1];
        float ep2 = e0 * WeP[k2] + e1 * WeP[256 + k2] + e2 * WeP[512 + k2]
                  + e3 * WeP[768 + k2] + e4 * WeP[1024 + k2];
        float z1 = g_xl[s * 256 + k1] + sxr[k1] + ep1;
        float z2 = g_xl[s * 256 + k2] + sxr[k2] + ep2;
        z1 = z1 >= 0.f ? z1 : 0.2f * z1;
        z2 = z2 >= 0.f ? z2 : 0.2f * z2;
        float v = z1 * a1 + z2 * a2;
        #pragma unroll
        for (int o = 16; o; o >>= 1) v += __shfl_down_sync(FULLMASK, v, o);
        if (lane == 0) {
            slog[i * 4 + hh] = v;
            if (hh == 0) ssrc[i] = s;
        }
    }
    __syncthreads();
    // phase 2: warp-parallel softmax — warp h handles head h, lanes stride edges
    if (t < 128) {
        int h = wid;   // 0..3
        float m = -1e30f;
        for (int i = lane; i < d; i += 32) m = fmaxf(m, slog[i * 4 + h]);
        #pragma unroll
        for (int o = 16; o; o >>= 1) m = fmaxf(m, __shfl_xor_sync(FULLMASK, m, o));
        float ssum = 0.f;
        for (int i = lane; i < d; i += 32) {
            float ex = __expf(slog[i * 4 + h] - m);
            slog[i * 4 + h] = ex;
            ssum += ex;
        }
        #pragma unroll
        for (int o = 16; o; o >>= 1) ssum += __shfl_xor_sync(FULLMASK, ssum, o);
        float inv = 1.f / (ssum + 1e-16f);
        for (int i = lane; i < d; i += 32) slog[i * 4 + h] *= inv;
    }
    __syncthreads();
    // phase 3: weighted aggregation (xl rows are L1-hot from phase 1)
    int h = t >> 6;
    float acc = 0.f;
    int i = 0;
    for (; i + 2 <= d; i += 2) {
        int s0 = ssrc[i], s1 = ssrc[i + 1];
        float w0 = slog[i * 4 + h], w1 = slog[(i + 1) * 4 + h];
        acc += g_xl[s0 * 256 + t] * w0;
        acc += g_xl[s1 * 256 + t] * w1;
    }
    if (i < d) acc += g_xl[ssrc[i] * 256 + t] * slog[i * 4 + h];
    g_out[n * 256 + t] = acc;   // GAT bias absorbed by BatchNorm — skipped
}

// ---------------- BatchNorm statistics ----------------
__global__ void zero_stats_k() {
    int t = threadIdx.x;
    g_csum[t] = 0.f;
    g_csq[t]  = 0.f;
}

__global__ void bnstat_k() {
    int t = threadIdx.x;  // 256 = channel
    int rows = (NN + gridDim.x - 1) / gridDim.x;
    int r0 = blockIdx.x * rows;
    int r1 = min(NN, r0 + rows);
    float s = 0.f, q = 0.f;
    for (int r = r0; r < r1; r++) {
        float v = g_out[r * 256 + t];
        s += v;
        q += v * v;
    }
    atomicAdd(&g_csum[t], s);
    atomicAdd(&g_csq[t], q);
}

// ---------------- pool + classifier (BN+leaky of layer 1 fused in) -------------
__global__ void pool_k(const float* __restrict__ W, const float* __restrict__ bb,
                       const float* __restrict__ gam, const float* __restrict__ bet,
                       float* __restrict__ outp) {
    int g = blockIdx.x;   // 128 graphs
    int t = threadIdx.x;  // 256 = channel
    float mu  = g_csum[t] * (1.f / NN);
    float var = g_csq[t] * (1.f / NN) - mu * mu;
    float rs = rsqrtf(var + 1e-5f) * gam[t];
    float bt = bet[t];
    float s = 0.f;
    int base = g * N_ROI;
    for (int r = 0; r < N_ROI; r++) {
        float v = g_out[(base + r) * 256 + t];
        v = (v - mu) * rs + bt;
        v = v >= 0.f ? v : 0.01f * v;
        s += v;
    }
    s *= (1.f / (float)N_ROI);
    float c0 = s * W[t * 2], c1 = s * W[t * 2 + 1];
    __shared__ float r0s[8], r1s[8];
    for (int o = 16; o; o >>= 1) {
        c0 += __shfl_down_sync(FULLMASK, c0, o);
        c1 += __shfl_down_sync(FULLMASK, c1, o);
    }
    if ((t & 31) == 0) { r0s[t >> 5] = c0; r1s[t >> 5] = c1; }
    __syncthreads();
    if (t == 0) {
        float a = 0.f, b2 = 0.f;
        for (int i = 0; i < 8; i++) { a += r0s[i]; b2 += r1s[i]; }
        outp[g * 2]     = a  + bb[0];
        outp[g * 2 + 1] = b2 + bb[1];
    }
}

// ---------------- launch --------------------------------------------------------
extern "C" void kernel_launch(void* const* d_in, const int* in_sizes, int n_in,
                              void* d_out, int out_size) {
    const float* x          = (const float*)d_in[0];
    const int*   edge_index = (const int*)  d_in[1];
    const float* edge_attr  = (const float*)d_in[2];
    const int*   node_group = (const int*)  d_in[4];
    const float* group_emb  = (const float*)d_in[5];
    const float* W_embed    = (const float*)d_in[6];
    const float* b_embed    = (const float*)d_in[7];
    const float* We_enc     = (const float*)d_in[8];
    const float* be_enc     = (const float*)d_in[9];
    const float* W1         = (const float*)d_in[10];
    const float* b1         = (const float*)d_in[11];
    const float* W2         = (const float*)d_in[12];
    const float* b2         = (const float*)d_in[13];
    const float* ln_g       = (const float*)d_in[14];
    const float* ln_b       = (const float*)d_in[15];
    const float* l0_Wl      = (const float*)d_in[16];
    const float* l0_Wr      = (const float*)d_in[17];
    const float* l0_We      = (const float*)d_in[18];
    const float* l0_att     = (const float*)d_in[19];
    const float* l0_bn_g    = (const float*)d_in[21];
    const float* l0_bn_b    = (const float*)d_in[22];
    const float* l1_Wl      = (const float*)d_in[23];
    const float* l1_Wr      = (const float*)d_in[24];
    const float* l1_We      = (const float*)d_in[25];
    const float* l1_att     = (const float*)d_in[26];
    const float* l1_bn_g    = (const float*)d_in[28];
    const float* l1_bn_b    = (const float*)d_in[29];
    const float* fc2_W      = (const float*)d_in[30];
    const float* fc2_b      = (const float*)d_in[31];

    const int* srcp = edge_index;
    const int* dstp = edge_index + EE;

    build_adj_k<<<(NN * 32 + 255) / 256, 256>>>(dstp);
    embed_k<<<NN, 64>>>(x, node_group, group_emb, W_embed, b_embed);
    gine_k<<<NN, 64>>>(srcp, edge_attr, We_enc, be_enc, W1, b1, W2, b2, ln_g, ln_b);

    // GAT layer 0
    xlxr0_k<<<NN / 16, 256>>>(l0_Wl, l0_Wr);
    gat_node_k<<<NN, 256>>>(srcp, edge_attr, l0_We, l0_att);
    zero_stats_k<<<1, 256>>>();
    bnstat_k<<<256, 256>>>();

    // GAT layer 1 (BN of layer 0 fused into xlxr1 input load)
    xlxr1_k<<<NN / 16, 256>>>(l1_Wl, l1_Wr, l0_bn_g, l0_bn_b);
    gat_node_k<<<NN, 256>>>(srcp, edge_attr, l1_We, l1_att);
    zero_stats_k<<<1, 256>>>();
    bnstat_k<<<256, 256>>>();

    // pool + classifier (BN of layer 1 fused in)
    pool_k<<<G, 256>>>(fc2_W, fc2_b, l1_bn_g, l1_bn_b, (float*)d_out);
}